// round 10
// baseline (speedup 1.0000x reference)
#include <cuda_runtime.h>

// Problem constants
#define BATCH 32
#define SEQ   2048
#define NPOS  (BATCH * SEQ)   // 65536 positions
#define M     10              // number of primes
#define NTAB  129             // sum of primes 2+3+5+7+11+13+17+19+23+29

// Tables (filled every launch by init kernel; deterministic, graph-capturable)
// g_tabW: { K*cos, K*sin }  with K = TEMP * log2(e)  (softmax logits in log2 domain)
// g_tabE: { cos, sin }      (re-encode templates)
__device__ float2 g_tabW[NTAB];
__device__ float2 g_tabE[NTAB];

__global__ void init_tables_kernel() {
    int idx = threadIdx.x;
    if (idx >= NTAB) return;
    const int primes[M] = {2, 3, 5, 7, 11, 13, 17, 19, 23, 29};
    int k = idx, p = 29;
    for (int pi = 0; pi < M; pi++) {
        if (k < primes[pi]) { p = primes[pi]; break; }
        k -= primes[pi];
    }
    double ang = 6.283185307179586476925287 * (double)k / (double)p;
    float c = (float)cos(ang), s = (float)sin(ang);  // matches numpy f64->f32 rounding
    const double K = 1000.0 * 1.4426950408889634074; // TEMP * log2(e)
    g_tabW[idx] = make_float2((float)((double)c * K), (float)((double)s * K));
    g_tabE[idx] = make_float2(c, s);
}

__device__ __forceinline__ float ex2f(float x) {
    float r; asm("ex2.approx.f32 %0, %1;" : "=f"(r) : "f"(x)); return r;
}
__device__ __forceinline__ float rcpf(float x) {
    float r; asm("rcp.approx.f32 %0, %1;" : "=f"(r) : "f"(x)); return r;
}

// ---- full-scalar path (small/medium primes) ----
template <int P, int PI, int OFF>
__device__ __forceinline__ void prime_scalar(
    int pos, const float2* __restrict__ a2, const float2* __restrict__ b2,
    float2* __restrict__ oAdd, float2* __restrict__ oSub, float2* __restrict__ oMul,
    const float2* __restrict__ shW, const float2* __restrict__ shE)
{
    const int idx = pos * M + PI;
    const float2 A = a2[idx], B = b2[idx];

    // add = a+b on circle, sub = a-b (conj b) -- share the 4 products
    {
        float t1 = A.x * B.x, t2 = A.y * B.y, t3 = A.y * B.x, t4 = A.x * B.y;
        oAdd[idx] = make_float2(t1 - t2, t3 + t4);
        oSub[idx] = make_float2(t1 + t2, t3 - t4);
    }

    // logits in log2 domain (tables pre-scaled by TEMP*log2e)
    float wa[P], wb[P];
#pragma unroll
    for (int i = 0; i < P; i++) {
        float2 t = shW[OFF + i];
        wa[i] = fmaf(A.x, t.x, A.y * t.y);
        wb[i] = fmaf(B.x, t.x, B.y * t.y);
    }

    // dual-accumulator max per side
    float ma0 = wa[0], mb0 = wb[0];
    float ma1 = (P > 1) ? wa[1] : wa[0];
    float mb1 = (P > 1) ? wb[1] : wb[0];
#pragma unroll
    for (int i = 2; i < P; i++) {
        if (i & 1) { ma1 = fmaxf(ma1, wa[i]); mb1 = fmaxf(mb1, wb[i]); }
        else       { ma0 = fmaxf(ma0, wa[i]); mb0 = fmaxf(mb0, wb[i]); }
    }
    const float mxa = fmaxf(ma0, ma1), mxb = fmaxf(mb0, mb1);

    // exp2 + sums (dual accumulators per side)
    float sa0 = 0.f, sa1 = 0.f, sb0 = 0.f, sb1 = 0.f;
#pragma unroll
    for (int i = 0; i < P; i++) {
        float ea = ex2f(wa[i] - mxa);
        float eb = ex2f(wb[i] - mxb);
        wa[i] = ea; wb[i] = eb;
        if (i & 1) { sa1 += ea; sb1 += eb; }
        else       { sa0 += ea; sb0 += eb; }
    }
    const float Sa = sa0 + sa1, Sb = sb0 + sb1;

    // dist over residues; i=0 / j=0 cross terms collapse onto residue 0
    float dist[P];
    dist[0] = fmaf(wa[0], Sb, fmaf(wb[0], Sa, -(wa[0] * wb[0])));
#pragma unroll
    for (int k = 1; k < P; k++) dist[k] = 0.f;
#pragma unroll
    for (int i = 1; i < P; i++) {
        const float wai = wa[i];
#pragma unroll
        for (int j = 1; j < P; j++) {
            const int k = (i * j) % P;   // bijection over 1..P-1 per i
            dist[k] = fmaf(wai, wb[j], dist[k]);
        }
    }

    // re-encode to circle (4 accumulators), normalize by (sum wa)*(sum wb)
    float X0 = 0.f, X1 = 0.f, Y0 = 0.f, Y1 = 0.f;
#pragma unroll
    for (int k = 0; k < P; k++) {
        float2 e = shE[OFF + k];
        if (k & 1) { X1 = fmaf(dist[k], e.x, X1); Y1 = fmaf(dist[k], e.y, Y1); }
        else       { X0 = fmaf(dist[k], e.x, X0); Y0 = fmaf(dist[k], e.y, Y0); }
    }
    const float inv = rcpf(Sa * Sb);
    oMul[idx] = make_float2((X0 + X1) * inv, (Y0 + Y1) * inv);
}

// ---- scalar low-register path (p=23,29): store wb only; recompute wa per outer-i ----
template <int P, int PI, int OFF>
__device__ __forceinline__ void prime_lowreg(
    int pos, const float2* __restrict__ a2, const float2* __restrict__ b2,
    float2* __restrict__ oAdd, float2* __restrict__ oSub, float2* __restrict__ oMul,
    const float2* __restrict__ shW, const float2* __restrict__ shE)
{
    const int idx = pos * M + PI;
    const float2 A = a2[idx], B = b2[idx];
    {
        float t1 = A.x * B.x, t2 = A.y * B.y, t3 = A.y * B.x, t4 = A.x * B.y;
        oAdd[idx] = make_float2(t1 - t2, t3 + t4);
        oSub[idx] = make_float2(t1 + t2, t3 - t4);
    }

    // pass 1: logits, maxes only (no weight storage)
    float ma0, ma1, mb0, mb1;
    {
        float2 t0 = shW[OFF + 0];
        ma0 = fmaf(A.x, t0.x, A.y * t0.y);
        mb0 = fmaf(B.x, t0.x, B.y * t0.y);
        float2 t1 = shW[OFF + 1];
        ma1 = fmaf(A.x, t1.x, A.y * t1.y);
        mb1 = fmaf(B.x, t1.x, B.y * t1.y);
    }
#pragma unroll
    for (int i = 2; i < P; i++) {
        float2 t = shW[OFF + i];
        float la = fmaf(A.x, t.x, A.y * t.y);
        float lb = fmaf(B.x, t.x, B.y * t.y);
        if (i & 1) { ma1 = fmaxf(ma1, la); mb1 = fmaxf(mb1, lb); }
        else       { ma0 = fmaxf(ma0, la); mb0 = fmaxf(mb0, lb); }
    }
    const float mxa = fmaxf(ma0, ma1), mxb = fmaxf(mb0, mb1);

    // pass 2: recompute logits, exp; store wb only; sums for both sides
    float wb[P];
    float Sa = 0.f, Sb = 0.f, wa0 = 0.f;
#pragma unroll
    for (int i = 0; i < P; i++) {
        float2 t = shW[OFF + i];
        float la = fmaf(A.x, t.x, A.y * t.y);
        float lb = fmaf(B.x, t.x, B.y * t.y);
        float ea = ex2f(la - mxa);
        float eb = ex2f(lb - mxb);
        if (i == 0) wa0 = ea;
        Sa += ea; Sb += eb;
        wb[i] = eb;
    }
    const float SaSb = Sa * Sb;

    // pass 3: dist; wa recomputed per outer-i (bit-identical rounding to pass 2)
    float dist[P];
    dist[0] = fmaf(wa0, Sb, fmaf(wb[0], Sa, -(wa0 * wb[0])));
#pragma unroll
    for (int k = 1; k < P; k++) dist[k] = 0.f;
#pragma unroll
    for (int i = 1; i < P; i++) {
        float2 t = shW[OFF + i];
        float la = fmaf(A.x, t.x, A.y * t.y);
        float wai = ex2f(la - mxa);
#pragma unroll
        for (int j = 1; j < P; j++) {
            const int k = (i * j) % P;
            dist[k] = fmaf(wai, wb[j], dist[k]);
        }
    }

    // re-encode + normalize
    float X0 = 0.f, X1 = 0.f, Y0 = 0.f, Y1 = 0.f;
#pragma unroll
    for (int k = 0; k < P; k++) {
        float2 e = shE[OFF + k];
        if (k & 1) { X1 = fmaf(dist[k], e.x, X1); Y1 = fmaf(dist[k], e.y, Y1); }
        else       { X0 = fmaf(dist[k], e.x, X0); Y0 = fmaf(dist[k], e.y, Y0); }
    }
    const float inv = rcpf(SaSb);
    oMul[idx] = make_float2((X0 + X1) * inv, (Y0 + Y1) * inv);
}

// 128 threads per block: threads 0-63 (grp 0) do primes {2,3,5,19,29},
// threads 64-127 (grp 1) do primes {7,11,13,17,23} for the SAME 64 positions.
// -> 4096 warps total (2x R8), warp-uniform branch, balanced ~2010 vs ~2036
// issue-ops/thread, and all writes to each output line come from one block.
// (128,6) -> 84-reg cap; lowreg variants keep p=23/29 peaks ~70 (no spill).
__global__ void __launch_bounds__(128, 6)
circle_kernel(const float* __restrict__ a, const float* __restrict__ b,
              float* __restrict__ out)
{
    __shared__ float2 shW[NTAB];
    __shared__ float2 shE[NTAB];
    for (int i = threadIdx.x; i < NTAB; i += 128) {
        shW[i] = g_tabW[i];
        shE[i] = g_tabE[i];
    }
    __syncthreads();

    const int tid = threadIdx.x;
    const int grp = tid >> 6;             // 0 or 1 (warp-uniform)
    const int pos = blockIdx.x * 64 + (tid & 63);

    const float2* a2 = (const float2*)a;
    const float2* b2 = (const float2*)b;
    float2* oAdd = (float2*)out;
    float2* oSub = oAdd + (size_t)NPOS * M;
    float2* oMul = oSub + (size_t)NPOS * M;

    // prime offsets into tables: 2:0 3:2 5:5 7:10 11:17 13:28 17:41 19:58 23:77 29:100
    if (grp == 0) {
        prime_scalar< 2, 0,   0>(pos, a2, b2, oAdd, oSub, oMul, shW, shE);
        prime_scalar< 3, 1,   2>(pos, a2, b2, oAdd, oSub, oMul, shW, shE);
        prime_scalar< 5, 2,   5>(pos, a2, b2, oAdd, oSub, oMul, shW, shE);
        prime_scalar<19, 7,  58>(pos, a2, b2, oAdd, oSub, oMul, shW, shE);
        prime_lowreg<29, 9, 100>(pos, a2, b2, oAdd, oSub, oMul, shW, shE);
    } else {
        prime_scalar< 7, 3,  10>(pos, a2, b2, oAdd, oSub, oMul, shW, shE);
        prime_scalar<11, 4,  17>(pos, a2, b2, oAdd, oSub, oMul, shW, shE);
        prime_scalar<13, 5,  28>(pos, a2, b2, oAdd, oSub, oMul, shW, shE);
        prime_scalar<17, 6,  41>(pos, a2, b2, oAdd, oSub, oMul, shW, shE);
        prime_lowreg<23, 8,  77>(pos, a2, b2, oAdd, oSub, oMul, shW, shE);
    }
}

extern "C" void kernel_launch(void* const* d_in, const int* in_sizes, int n_in,
                              void* d_out, int out_size) {
    const float* a = (const float*)d_in[0];
    const float* b = (const float*)d_in[1];
    float* out = (float*)d_out;
    init_tables_kernel<<<1, 160>>>();
    circle_kernel<<<NPOS / 64, 128>>>(a, b, out);
}